// round 15
// baseline (speedup 1.0000x reference)
#include <cuda_runtime.h>
#include <mma.h>
#include <cstdint>
#include <cstddef>

using namespace nvcuda;

#define Bb 32
#define Ss 2048
#define Ii 256
#define Hh 256
#define G4 1024   // 4*H

__device__ __align__(16) float g_P[(size_t)Bb * Ss * G4];

// ---------------- helpers ----------------
__device__ __forceinline__ void ffma2(unsigned long long &d, unsigned long long a, unsigned long long b) {
    asm volatile("fma.rn.f32x2 %0, %1, %2, %0;" : "+l"(d) : "l"(a), "l"(b));
}
__device__ __forceinline__ unsigned long long add2(unsigned long long a, unsigned long long b) {
    unsigned long long r; asm("add.rn.f32x2 %0, %1, %2;" : "=l"(r) : "l"(a), "l"(b)); return r;
}
__device__ __forceinline__ unsigned long long pk2(float x, float y) {
    unsigned long long r; asm("mov.b64 %0, {%1, %2};" : "=l"(r) : "f"(x), "f"(y)); return r;
}
__device__ __forceinline__ float2 upk2(unsigned long long v) {
    float2 f; asm("mov.b64 {%0, %1}, %2;" : "=f"(f.x), "=f"(f.y) : "l"(v)); return f;
}
__device__ __forceinline__ float ex2f(float x) {
    float r; asm("ex2.approx.ftz.f32 %0, %1;" : "=f"(r) : "f"(x)); return r;
}
__device__ __forceinline__ float rcpf(float x) {
    float r; asm("rcp.approx.ftz.f32 %0, %1;" : "=f"(r) : "f"(x)); return r;
}
#define L2E 1.4426950408889634f
// tanh(x) = 1 - 2/(1+e^{2x})
__device__ __forceinline__ float tanh_f(float x) {
    return fmaf(-2.0f, rcpf(1.0f + ex2f(2.0f * L2E * x)), 1.0f);
}

__device__ __forceinline__ void cp16(void* dst, const void* src) {
    uint32_t d = (uint32_t)__cvta_generic_to_shared(dst);
    asm volatile("cp.async.cg.shared.global [%0], [%1], 16;" :: "r"(d), "l"(src) : "memory");
}
// Poll at CTA scope (cheap). Data arrives via st.async (async proxy); the
// cta-acquire on the flipped mbarrier makes it visible.
__device__ __forceinline__ void mbar_wait(uint32_t mbar, uint32_t parity) {
    asm volatile(
        "{\n\t.reg .pred P1;\n\t"
        "WAITL_%=:\n\t"
        "mbarrier.try_wait.parity.acquire.cta.shared::cta.b64 P1, [%0], %1, 0x989680;\n\t"
        "@!P1 bra WAITL_%=;\n\t}"
        :: "r"(mbar), "r"(parity) : "memory");
}
__device__ __forceinline__ void mbar_expect(uint32_t mbar, uint32_t bytes) {
    asm volatile("mbarrier.arrive.expect_tx.shared.b64 _, [%0], %1;"
                 :: "r"(mbar), "r"(bytes) : "memory");
}

// ---------------- kernel 1: x-projection GEMM (smem-staged tf32 wmma) ----------------
// Also zeroes the two trailing (1,B,H) output tensors (folds the old zero_tail
// kernel in, so the CUDA graph has exactly 2 nodes).
#define XK 16
#define NKC (Ii / XK)
__global__ __launch_bounds__(256, 2) void xproj_kernel(const float* __restrict__ x,
                                                       const float* __restrict__ W,
                                                       float* __restrict__ out,
                                                       int tail_start, int tail_len) {
    __shared__ __align__(16) float sA[2][128][XK + 4];
    __shared__ __align__(16) float sB[2][XK][128 + 4];

    const int tid = threadIdx.x;
    // fold-in: zero the trailing outputs (16K floats over a 1M-thread grid)
    {
        int fid = (blockIdx.y * gridDim.x + blockIdx.x) * blockDim.x + tid;
        if (fid < tail_len) out[tail_start + fid] = 0.0f;
    }

    const int wid = tid >> 5;
    const int wm = wid & 3, wn = wid >> 2;
    const int m0 = blockIdx.y * 128;
    const int n0 = blockIdx.x * 128;

    wmma::fragment<wmma::accumulator, 16, 16, 8, float> acc[2][4];
#pragma unroll
    for (int i = 0; i < 2; i++)
#pragma unroll
        for (int j = 0; j < 4; j++) wmma::fill_fragment(acc[i][j], 0.0f);

    auto issue = [&](int buf, int kc) {
#pragma unroll
        for (int u = 0; u < 2; u++) {
            int v = tid + u * 256;
            int r = v >> 2, kq = v & 3;
            cp16(&sA[buf][r][4 * kq], x + (size_t)(m0 + r) * Ii + kc * XK + 4 * kq);
            int kr = v >> 5, cq = v & 31;
            cp16(&sB[buf][kr][4 * cq], W + (size_t)(kc * XK + kr) * G4 + n0 + 4 * cq);
        }
    };

    issue(0, 0);
    asm volatile("cp.async.commit_group;");

    for (int kc = 0; kc < NKC; kc++) {
        int buf = kc & 1;
        if (kc + 1 < NKC) {
            issue(buf ^ 1, kc + 1);
            asm volatile("cp.async.commit_group;");
            asm volatile("cp.async.wait_group 1;");
        } else {
            asm volatile("cp.async.wait_group 0;");
        }
        __syncthreads();
#pragma unroll
        for (int ks = 0; ks < XK; ks += 8) {
            wmma::fragment<wmma::matrix_a, 16, 16, 8, wmma::precision::tf32, wmma::row_major> af[2];
            wmma::fragment<wmma::matrix_b, 16, 16, 8, wmma::precision::tf32, wmma::row_major> bf[4];
#pragma unroll
            for (int i = 0; i < 2; i++) {
                wmma::load_matrix_sync(af[i], &sA[buf][wm * 32 + 16 * i][ks], XK + 4);
#pragma unroll
                for (int e = 0; e < af[i].num_elements; e++) af[i].x[e] = wmma::__float_to_tf32(af[i].x[e]);
            }
#pragma unroll
            for (int j = 0; j < 4; j++) {
                wmma::load_matrix_sync(bf[j], &sB[buf][ks][wn * 64 + 16 * j], 128 + 4);
#pragma unroll
                for (int e = 0; e < bf[j].num_elements; e++) bf[j].x[e] = wmma::__float_to_tf32(bf[j].x[e]);
            }
#pragma unroll
            for (int i = 0; i < 2; i++)
#pragma unroll
                for (int j = 0; j < 4; j++) wmma::mma_sync(acc[i][j], af[i], bf[j], acc[i][j]);
        }
        __syncthreads();
    }
#pragma unroll
    for (int i = 0; i < 2; i++)
#pragma unroll
        for (int j = 0; j < 4; j++)
            wmma::store_matrix_sync(g_P + (size_t)(m0 + wm * 32 + 16 * i) * G4 + n0 + wn * 64 + 16 * j,
                                    acc[i][j], G4, wmma::mem_row_major);
}

// ---------------- kernel 2: recurrent chain (R9 protocol -- best measured) ----------------
// 16 clusters x 8 CTAs, 2 batches/cluster, 512 thr/CTA. CTA owns 32 h-cols.
// Warp w owns h-cols 2w,2w+1. Lane = hc(1b) | grp(1b) | lk(3b).
// Weights in regs (2 gates x 32 rows x f32x2).
// Sync: st.async + mbarrier complete_tx (2048 B/CTA/phase, hardware-counted).
// Each warp's lane0 re-arms expect_tx(+128B) on the mbar it just waited on.
// Polling is cta-scope acquire. No cluster barrier / syncthreads in the loop.
__global__ void __cluster_dims__(8, 1, 1) __launch_bounds__(512, 1)
lstm_rec(const float* __restrict__ W, const float* __restrict__ bias,
         const float* __restrict__ h0, const float* __restrict__ c0,
         float* __restrict__ out) {
    __shared__ __align__(16) float h_sm[2 * 2 * Hh];     // [parity][batch][256]
    __shared__ __align__(8) unsigned long long mbar[2];

    const int tid = threadIdx.x;
    uint32_t rk; asm("mov.u32 %0, %%cluster_ctarank;" : "=r"(rk));
    const int b0 = (blockIdx.x >> 3) * 2;
    const int w = tid >> 5, lane = tid & 31;
    const int hc = lane >> 4, grp = (lane >> 3) & 1, lk = lane & 7;
    const int hcol = (int)rk * 32 + 2 * w + hc;

    // weights: gates grp*2, grp*2+1; rows 32i+4lk+{0..3}
    unsigned long long wreg[2][16];
#pragma unroll
    for (int gg = 0; gg < 2; gg++) {
        const float* Wc = W + (size_t)(grp * 2 + gg) * 256 + hcol;
#pragma unroll
        for (int i = 0; i < 8; i++) {
            const float* p = Wc + (size_t)(256 + 32 * i + 4 * lk) * G4;
            wreg[gg][2 * i]     = pk2(p[0], p[G4]);
            wreg[gg][2 * i + 1] = pk2(p[2 * (size_t)G4], p[3 * (size_t)G4]);
        }
    }

    // activation-task mapping (task lanes lk<4; gsel clamped in-bounds)
    const int gsel = grp * 2 + ((lk >> 1) & 1);
    const int bsel = lk & 1;
    const float bv = bias[gsel * 256 + hcol];
    const size_t prow = ((size_t)(b0 + bsel) * Ss) * G4 + gsel * 256 + hcol;
    const float ymL = (gsel == 2) ? 2.0f * L2E : -L2E;
    const float al  = (gsel == 2) ? 1.0f : 0.0f;
    const float be  = (gsel == 2) ? -2.0f : 1.0f;

    // combine lanes: lanes 4,5 (hc=0) and 20,21 (hc=1); batch = lane&1
    const bool comb = ((lane & 14) == 4);
    const int bc = lane & 1;
    float creg = comb ? c0[(size_t)(b0 + bc) * Hh + hcol] : 0.0f;
    const uint32_t lane_off = (uint32_t)(bc * 256 + hcol) * 4;

    const uint32_t hbase = (uint32_t)__cvta_generic_to_shared(h_sm);
    const uint32_t mbase = (uint32_t)__cvta_generic_to_shared(mbar);
    uint32_t htgt[8], mbtgt[8];
#pragma unroll
    for (int rr = 0; rr < 8; rr++) {
        asm("mapa.shared::cluster.u32 %0, %1, %2;" : "=r"(htgt[rr]) : "r"(hbase), "r"(rr));
        asm("mapa.shared::cluster.u32 %0, %1, %2;" : "=r"(mbtgt[rr]) : "r"(mbase), "r"(rr));
    }

    if (tid == 0) {
        asm volatile("mbarrier.init.shared.b64 [%0], %1;" :: "r"(mbase), "r"(16u) : "memory");
        asm volatile("mbarrier.init.shared.b64 [%0], %1;" :: "r"(mbase + 8), "r"(16u) : "memory");
        asm volatile("fence.mbarrier_init.release.cluster;" ::: "memory");
    }
    __syncthreads();
    // initial arming: every warp contributes 128 B expectation to BOTH parities
    if (lane == 0) {
        mbar_expect(mbase, 128u);
        mbar_expect(mbase + 8, 128u);
    }
    {   // seed h(0) into parity-0 buffer
        int b = tid >> 8, r = tid & 255;
        h_sm[b * Hh + r] = h0[(size_t)(b0 + b) * Hh + r];
    }
    asm volatile("barrier.cluster.arrive.aligned;" ::: "memory");
    asm volatile("barrier.cluster.wait.aligned;" ::: "memory");

    float pc = g_P[prow];  // P(t=0) for this lane's (gate,batch)
    for (int t = 0; t < Ss; t++) {
        const int par = t & 1;
        if (t > 0) {
            uint32_t mb = mbase + par * 8;
            mbar_wait(mb, ((uint32_t)(t - 1) >> 1) & 1u);
            if (lane == 0) mbar_expect(mb, 128u);   // re-arm for h(t+2)
        }
        float pf = g_P[prow + (size_t)((t + 1 < Ss) ? t + 1 : t) * G4];

        // ---- matvec: 2 gates x 2 batches, rows 32i+4lk+{0..3} ----
        unsigned long long a000 = 0, a001 = 0, a010 = 0, a011 = 0;
        unsigned long long a100 = 0, a101 = 0, a110 = 0, a111 = 0;
        const ulonglong2* hb0 = (const ulonglong2*)(h_sm + par * 2 * Hh);
        const ulonglong2* hb1 = hb0 + (Hh / 4);
#pragma unroll
        for (int i = 0; i < 8; i++) {
            ulonglong2 v0 = hb0[8 * i + lk];
            ulonglong2 v1 = hb1[8 * i + lk];
            ffma2(a000, wreg[0][2 * i], v0.x);  ffma2(a001, wreg[0][2 * i + 1], v0.y);
            ffma2(a100, wreg[1][2 * i], v0.x);  ffma2(a101, wreg[1][2 * i + 1], v0.y);
            ffma2(a010, wreg[0][2 * i], v1.x);  ffma2(a011, wreg[0][2 * i + 1], v1.y);
            ffma2(a110, wreg[1][2 * i], v1.x);  ffma2(a111, wreg[1][2 * i + 1], v1.y);
        }
        // packed pair-merge (add.rn.f32x2), then one unpack+add per value
        float2 f;
        f = upk2(add2(a000, a001)); float s00 = f.x + f.y;
        f = upk2(add2(a010, a011)); float s01 = f.x + f.y;
        f = upk2(add2(a100, a101)); float s10 = f.x + f.y;
        f = upk2(add2(a110, a111)); float s11 = f.x + f.y;
#pragma unroll
        for (int d = 1; d <= 4; d <<= 1) {
            s00 += __shfl_xor_sync(0xffffffffu, s00, d);
            s01 += __shfl_xor_sync(0xffffffffu, s01, d);
            s10 += __shfl_xor_sync(0xffffffffu, s10, d);
            s11 += __shfl_xor_sync(0xffffffffu, s11, d);
        }
        // activation on 16 task lanes (lk<4): z=tanh(pre+P+b), then gate act
        float pre = (lk >> 1) ? (bsel ? s11 : s10) : (bsel ? s01 : s00);
        float z1 = tanh_f(pre + pc + bv);
        float act = fmaf(be, rcpf(1.0f + ex2f(ymL * z1)), al);
        pc = pf;

        // gather i,f,g,o for (hc, batch=bc) via idx-shfl
        int base = (lane & 16);  // hc*16
        float ig_ = __shfl_sync(0xffffffffu, act, base + bc);
        float fg_ = __shfl_sync(0xffffffffu, act, base + 2 + bc);
        float gg_ = __shfl_sync(0xffffffffu, act, base + 8 + bc);
        float og_ = __shfl_sync(0xffffffffu, act, base + 10 + bc);

        if (comb) {
            creg = fmaf(fg_, creg, ig_ * gg_);
            float hnew = tanh_f(creg) * og_;
            out[((size_t)(b0 + bc) * Ss + t) * Hh + hcol] = hnew;
            if (t + 1 < Ss) {
                uint32_t off = (uint32_t)((par ^ 1) * 2048) + lane_off;
                uint32_t mboff = (uint32_t)((par ^ 1) * 8);
#pragma unroll
                for (int rr = 0; rr < 8; rr++)
                    asm volatile(
                        "st.async.weak.shared::cluster.mbarrier::complete_tx::bytes.f32 [%0], %1, [%2];"
                        :: "r"(htgt[rr] + off), "f"(hnew), "r"(mbtgt[rr] + mboff) : "memory");
            }
        }
    }
    asm volatile("barrier.cluster.arrive.aligned;" ::: "memory");
    asm volatile("barrier.cluster.wait.aligned;" ::: "memory");
}

extern "C" void kernel_launch(void* const* d_in, const int* in_sizes, int n_in,
                              void* d_out, int out_size) {
    const float* x    = (const float*)d_in[0];
    const float* h0   = (const float*)d_in[1];
    const float* c0   = (const float*)d_in[2];
    const float* W    = (const float*)d_in[3];
    const float* bias = (const float*)d_in[4];
    float* out = (float*)d_out;

    int main_elems = Bb * Ss * Hh;
    int tail = out_size - main_elems;

    dim3 gx(G4 / 128, (Bb * Ss) / 128);
    xproj_kernel<<<gx, 256>>>(x, W, out, main_elems, tail > 0 ? tail : 0);
    lstm_rec<<<128, 512>>>(W, bias, h0, c0, out);
}

// round 16
// speedup vs baseline: 1.6026x; 1.6026x over previous
#include <cuda_runtime.h>
#include <mma.h>
#include <cstdint>
#include <cstddef>

using namespace nvcuda;

#define Bb 32
#define Ss 2048
#define Ii 256
#define Hh 256
#define G4 1024   // 4*H

__device__ __align__(16) float g_P[(size_t)Bb * Ss * G4];

// ---------------- helpers ----------------
__device__ __forceinline__ void ffma2(unsigned long long &d, unsigned long long a, unsigned long long b) {
    asm volatile("fma.rn.f32x2 %0, %1, %2, %0;" : "+l"(d) : "l"(a), "l"(b));
}
__device__ __forceinline__ unsigned long long pk2(float x, float y) {
    unsigned long long r; asm("mov.b64 %0, {%1, %2};" : "=l"(r) : "f"(x), "f"(y)); return r;
}
__device__ __forceinline__ float2 upk2(unsigned long long v) {
    float2 f; asm("mov.b64 {%0, %1}, %2;" : "=f"(f.x), "=f"(f.y) : "l"(v)); return f;
}
__device__ __forceinline__ float ex2f(float x) {
    float r; asm("ex2.approx.ftz.f32 %0, %1;" : "=f"(r) : "f"(x)); return r;
}
__device__ __forceinline__ float rcpf(float x) {
    float r; asm("rcp.approx.ftz.f32 %0, %1;" : "=f"(r) : "f"(x)); return r;
}
#define L2E 1.4426950408889634f
// tanh(x) = 1 - 2/(1+e^{2x})
__device__ __forceinline__ float tanh_f(float x) {
    return fmaf(-2.0f, rcpf(1.0f + ex2f(2.0f * L2E * x)), 1.0f);
}

__device__ __forceinline__ void cp16(void* dst, const void* src) {
    uint32_t d = (uint32_t)__cvta_generic_to_shared(dst);
    asm volatile("cp.async.cg.shared.global [%0], [%1], 16;" :: "r"(d), "l"(src) : "memory");
}
// Poll at CTA scope. Data arrives via st.async (async proxy); the cta-acquire
// on the flipped mbarrier + __syncthreads makes it visible CTA-wide.
__device__ __forceinline__ void mbar_wait(uint32_t mbar, uint32_t parity) {
    asm volatile(
        "{\n\t.reg .pred P1;\n\t"
        "WAITL_%=:\n\t"
        "mbarrier.try_wait.parity.acquire.cta.shared::cta.b64 P1, [%0], %1, 0x989680;\n\t"
        "@!P1 bra WAITL_%=;\n\t}"
        :: "r"(mbar), "r"(parity) : "memory");
}
__device__ __forceinline__ void mbar_expect(uint32_t mbar, uint32_t bytes) {
    asm volatile("mbarrier.arrive.expect_tx.shared.b64 _, [%0], %1;"
                 :: "r"(mbar), "r"(bytes) : "memory");
}

// ---------------- kernel 1: x-projection GEMM (smem-staged tf32 wmma) ----------------
// Also zeroes the two trailing (1,B,H) output tensors (2-node graph so ncu's
// capture window lands on lstm_rec).
#define XK 16
#define NKC (Ii / XK)
__global__ __launch_bounds__(256, 2) void xproj_kernel(const float* __restrict__ x,
                                                       const float* __restrict__ W,
                                                       float* __restrict__ out,
                                                       int tail_start, int tail_len) {
    __shared__ __align__(16) float sA[2][128][XK + 4];
    __shared__ __align__(16) float sB[2][XK][128 + 4];

    const int tid = threadIdx.x;
    {
        int fid = (blockIdx.y * gridDim.x + blockIdx.x) * blockDim.x + tid;
        if (fid < tail_len) out[tail_start + fid] = 0.0f;
    }

    const int wid = tid >> 5;
    const int wm = wid & 3, wn = wid >> 2;
    const int m0 = blockIdx.y * 128;
    const int n0 = blockIdx.x * 128;

    wmma::fragment<wmma::accumulator, 16, 16, 8, float> acc[2][4];
#pragma unroll
    for (int i = 0; i < 2; i++)
#pragma unroll
        for (int j = 0; j < 4; j++) wmma::fill_fragment(acc[i][j], 0.0f);

    auto issue = [&](int buf, int kc) {
#pragma unroll
        for (int u = 0; u < 2; u++) {
            int v = tid + u * 256;
            int r = v >> 2, kq = v & 3;
            cp16(&sA[buf][r][4 * kq], x + (size_t)(m0 + r) * Ii + kc * XK + 4 * kq);
            int kr = v >> 5, cq = v & 31;
            cp16(&sB[buf][kr][4 * cq], W + (size_t)(kc * XK + kr) * G4 + n0 + 4 * cq);
        }
    };

    issue(0, 0);
    asm volatile("cp.async.commit_group;");

    for (int kc = 0; kc < NKC; kc++) {
        int buf = kc & 1;
        if (kc + 1 < NKC) {
            issue(buf ^ 1, kc + 1);
            asm volatile("cp.async.commit_group;");
            asm volatile("cp.async.wait_group 1;");
        } else {
            asm volatile("cp.async.wait_group 0;");
        }
        __syncthreads();
#pragma unroll
        for (int ks = 0; ks < XK; ks += 8) {
            wmma::fragment<wmma::matrix_a, 16, 16, 8, wmma::precision::tf32, wmma::row_major> af[2];
            wmma::fragment<wmma::matrix_b, 16, 16, 8, wmma::precision::tf32, wmma::row_major> bf[4];
#pragma unroll
            for (int i = 0; i < 2; i++) {
                wmma::load_matrix_sync(af[i], &sA[buf][wm * 32 + 16 * i][ks], XK + 4);
#pragma unroll
                for (int e = 0; e < af[i].num_elements; e++) af[i].x[e] = wmma::__float_to_tf32(af[i].x[e]);
            }
#pragma unroll
            for (int j = 0; j < 4; j++) {
                wmma::load_matrix_sync(bf[j], &sB[buf][ks][wn * 64 + 16 * j], 128 + 4);
#pragma unroll
                for (int e = 0; e < bf[j].num_elements; e++) bf[j].x[e] = wmma::__float_to_tf32(bf[j].x[e]);
            }
#pragma unroll
            for (int i = 0; i < 2; i++)
#pragma unroll
                for (int j = 0; j < 4; j++) wmma::mma_sync(acc[i][j], af[i], bf[j], acc[i][j]);
        }
        __syncthreads();
    }
#pragma unroll
    for (int i = 0; i < 2; i++)
#pragma unroll
        for (int j = 0; j < 4; j++)
            wmma::store_matrix_sync(g_P + (size_t)(m0 + wm * 32 + 16 * i) * G4 + n0 + wn * 64 + 16 * j,
                                    acc[i][j], G4, wmma::mem_row_major);
}

// ---------------- kernel 2: recurrent chain (R9 compute, delegated wait) ----------------
// 16 clusters x 8 CTAs, 2 batches/cluster, 512 thr/CTA. CTA owns 32 h-cols.
// Warp w owns h-cols 2w,2w+1. Lane = hc(1b) | grp(1b) | lk(3b).
// Weights in regs (2 gates x 32 rows x f32x2).
// Sync: st.async + mbarrier complete_tx (2048 B/CTA/phase). ONLY WARP 0 polls
// the mbarrier (removes 15 warps of poll traffic from the contended mbar
// word); everyone else is released by one __syncthreads(). tid0 re-arms
// expect_tx(2048) after the flip (count=1; expect/complete commute in-phase).
__global__ void __cluster_dims__(8, 1, 1) __launch_bounds__(512, 1)
lstm_rec(const float* __restrict__ W, const float* __restrict__ bias,
         const float* __restrict__ h0, const float* __restrict__ c0,
         float* __restrict__ out) {
    __shared__ __align__(16) float h_sm[2 * 2 * Hh];     // [parity][batch][256]
    __shared__ __align__(8) unsigned long long mbar[2];

    const int tid = threadIdx.x;
    uint32_t rk; asm("mov.u32 %0, %%cluster_ctarank;" : "=r"(rk));
    const int b0 = (blockIdx.x >> 3) * 2;
    const int w = tid >> 5, lane = tid & 31;
    const int hc = lane >> 4, grp = (lane >> 3) & 1, lk = lane & 7;
    const int hcol = (int)rk * 32 + 2 * w + hc;

    // weights: gates grp*2, grp*2+1; rows 32i+4lk+{0..3}
    unsigned long long wreg[2][16];
#pragma unroll
    for (int gg = 0; gg < 2; gg++) {
        const float* Wc = W + (size_t)(grp * 2 + gg) * 256 + hcol;
#pragma unroll
        for (int i = 0; i < 8; i++) {
            const float* p = Wc + (size_t)(256 + 32 * i + 4 * lk) * G4;
            wreg[gg][2 * i]     = pk2(p[0], p[G4]);
            wreg[gg][2 * i + 1] = pk2(p[2 * (size_t)G4], p[3 * (size_t)G4]);
        }
    }

    // activation-task mapping (task lanes lk<4; gsel clamped in-bounds)
    const int gsel = grp * 2 + ((lk >> 1) & 1);
    const int bsel = lk & 1;
    const float bv = bias[gsel * 256 + hcol];
    const size_t prow = ((size_t)(b0 + bsel) * Ss) * G4 + gsel * 256 + hcol;
    const float ymL = (gsel == 2) ? 2.0f * L2E : -L2E;
    const float al  = (gsel == 2) ? 1.0f : 0.0f;
    const float be  = (gsel == 2) ? -2.0f : 1.0f;

    // combine lanes: lanes 4,5 (hc=0) and 20,21 (hc=1); batch = lane&1
    const bool comb = ((lane & 14) == 4);
    const int bc = lane & 1;
    float creg = comb ? c0[(size_t)(b0 + bc) * Hh + hcol] : 0.0f;
    const uint32_t lane_off = (uint32_t)(bc * 256 + hcol) * 4;

    const uint32_t hbase = (uint32_t)__cvta_generic_to_shared(h_sm);
    const uint32_t mbase = (uint32_t)__cvta_generic_to_shared(mbar);
    uint32_t htgt[8], mbtgt[8];
#pragma unroll
    for (int rr = 0; rr < 8; rr++) {
        asm("mapa.shared::cluster.u32 %0, %1, %2;" : "=r"(htgt[rr]) : "r"(hbase), "r"(rr));
        asm("mapa.shared::cluster.u32 %0, %1, %2;" : "=r"(mbtgt[rr]) : "r"(mbase), "r"(rr));
    }

    if (tid == 0) {
        asm volatile("mbarrier.init.shared.b64 [%0], %1;" :: "r"(mbase), "r"(1u) : "memory");
        asm volatile("mbarrier.init.shared.b64 [%0], %1;" :: "r"(mbase + 8), "r"(1u) : "memory");
        mbar_expect(mbase, 2048u);       // arms phase for h(2)
        mbar_expect(mbase + 8, 2048u);   // arms phase for h(1)
        asm volatile("fence.mbarrier_init.release.cluster;" ::: "memory");
    }
    {   // seed h(0) into parity-0 buffer
        int b = tid >> 8, r = tid & 255;
        h_sm[b * Hh + r] = h0[(size_t)(b0 + b) * Hh + r];
    }
    asm volatile("barrier.cluster.arrive.aligned;" ::: "memory");
    asm volatile("barrier.cluster.wait.aligned;" ::: "memory");

    float pc = g_P[prow];  // P(t=0) for this lane's (gate,batch)
    for (int t = 0; t < Ss; t++) {
        const int par = t & 1;
        if (t > 0) {
            if (w == 0) {                      // ONLY warp 0 polls the mbar
                uint32_t mb = mbase + par * 8;
                mbar_wait(mb, ((uint32_t)(t - 1) >> 1) & 1u);
                if (lane == 0) mbar_expect(mb, 2048u);   // re-arm for h(t+2)
            }
            __syncthreads();                   // release all 16 warps
        }
        float pf = g_P[prow + (size_t)((t + 1 < Ss) ? t + 1 : t) * G4];

        // ---- matvec: 2 gates x 2 batches, rows 32i+4lk+{0..3} ----
        unsigned long long a000 = 0, a001 = 0, a010 = 0, a011 = 0;
        unsigned long long a100 = 0, a101 = 0, a110 = 0, a111 = 0;
        const ulonglong2* hb0 = (const ulonglong2*)(h_sm + par * 2 * Hh);
        const ulonglong2* hb1 = hb0 + (Hh / 4);
#pragma unroll
        for (int i = 0; i < 8; i++) {
            ulonglong2 v0 = hb0[8 * i + lk];
            ulonglong2 v1 = hb1[8 * i + lk];
            ffma2(a000, wreg[0][2 * i], v0.x);  ffma2(a001, wreg[0][2 * i + 1], v0.y);
            ffma2(a100, wreg[1][2 * i], v0.x);  ffma2(a101, wreg[1][2 * i + 1], v0.y);
            ffma2(a010, wreg[0][2 * i], v1.x);  ffma2(a011, wreg[0][2 * i + 1], v1.y);
            ffma2(a110, wreg[1][2 * i], v1.x);  ffma2(a111, wreg[1][2 * i + 1], v1.y);
        }
        float2 f;
        f = upk2(a000); float s00 = f.x + f.y; f = upk2(a001); s00 += f.x + f.y;
        f = upk2(a010); float s01 = f.x + f.y; f = upk2(a011); s01 += f.x + f.y;
        f = upk2(a100); float s10 = f.x + f.y; f = upk2(a101); s10 += f.x + f.y;
        f = upk2(a110); float s11 = f.x + f.y; f = upk2(a111); s11 += f.x + f.y;
#pragma unroll
        for (int d = 1; d <= 4; d <<= 1) {
            s00 += __shfl_xor_sync(0xffffffffu, s00, d);
            s01 += __shfl_xor_sync(0xffffffffu, s01, d);
            s10 += __shfl_xor_sync(0xffffffffu, s10, d);
            s11 += __shfl_xor_sync(0xffffffffu, s11, d);
        }
        // activation on 16 task lanes (lk<4): z=tanh(pre+P+b), then gate act
        float pre = (lk >> 1) ? (bsel ? s11 : s10) : (bsel ? s01 : s00);
        float z1 = tanh_f(pre + pc + bv);
        float act = fmaf(be, rcpf(1.0f + ex2f(ymL * z1)), al);
        pc = pf;

        // gather i,f,g,o for (hc, batch=bc) via idx-shfl
        int base = (lane & 16);  // hc*16
        float ig_ = __shfl_sync(0xffffffffu, act, base + bc);
        float fg_ = __shfl_sync(0xffffffffu, act, base + 2 + bc);
        float gg_ = __shfl_sync(0xffffffffu, act, base + 8 + bc);
        float og_ = __shfl_sync(0xffffffffu, act, base + 10 + bc);

        if (comb) {
            creg = fmaf(fg_, creg, ig_ * gg_);
            float hnew = tanh_f(creg) * og_;
            out[((size_t)(b0 + bc) * Ss + t) * Hh + hcol] = hnew;
            if (t + 1 < Ss) {
                uint32_t off = (uint32_t)((par ^ 1) * 2048) + lane_off;
                uint32_t mboff = (uint32_t)((par ^ 1) * 8);
#pragma unroll
                for (int rr = 0; rr < 8; rr++)
                    asm volatile(
                        "st.async.weak.shared::cluster.mbarrier::complete_tx::bytes.f32 [%0], %1, [%2];"
                        :: "r"(htgt[rr] + off), "f"(hnew), "r"(mbtgt[rr] + mboff) : "memory");
            }
        }
    }
    asm volatile("barrier.cluster.arrive.aligned;" ::: "memory");
    asm volatile("barrier.cluster.wait.aligned;" ::: "memory");
}

extern "C" void kernel_launch(void* const* d_in, const int* in_sizes, int n_in,
                              void* d_out, int out_size) {
    const float* x    = (const float*)d_in[0];
    const float* h0   = (const float*)d_in[1];
    const float* c0   = (const float*)d_in[2];
    const float* W    = (const float*)d_in[3];
    const float* bias = (const float*)d_in[4];
    float* out = (float*)d_out;

    int main_elems = Bb * Ss * Hh;
    int tail = out_size - main_elems;

    dim3 gx(G4 / 128, (Bb * Ss) / 128);
    xproj_kernel<<<gx, 256>>>(x, W, out, main_elems, tail > 0 ? tail : 0);
    lstm_rec<<<128, 512>>>(W, bias, h0, c0, out);
}